// round 1
// baseline (speedup 1.0000x reference)
#include <cuda_runtime.h>
#include <math.h>

#define BATCH 256
#define NF 512
#define DM 1024
#define DH 512   // d_model/2

// -------- scratch (no allocations allowed) --------
__device__ float g_phi[BATCH * DM];
__device__ float g_c[BATCH * DM];
__device__ float g_s[BATCH * DM];
__device__ float g_ca[BATCH * DM];
__device__ float g_coupled[BATCH * DM];
__device__ float g_gate[BATCH * DH];

typedef unsigned long long u64;

// -------- packed fp32x2 helpers (Blackwell FFMA2 path) --------
__device__ __forceinline__ u64 f32x2_fma(u64 a, u64 b, u64 c) {
    u64 d;
    asm("fma.rn.f32x2 %0, %1, %2, %3;" : "=l"(d) : "l"(a), "l"(b), "l"(c));
    return d;
}
__device__ __forceinline__ u64 f32x2_mul(u64 a, u64 b) {
    u64 d;
    asm("mul.rn.f32x2 %0, %1, %2;" : "=l"(d) : "l"(a), "l"(b));
    return d;
}
__device__ __forceinline__ u64 f32x2_add(u64 a, u64 b) {
    u64 d;
    asm("add.rn.f32x2 %0, %1, %2;" : "=l"(d) : "l"(a), "l"(b));
    return d;
}
__device__ __forceinline__ u64 pack_dup(float v) {
    u64 r;
    asm("mov.b64 %0, {%1, %2};" : "=l"(r) : "f"(v), "f"(v));
    return r;
}
__device__ __forceinline__ float2 unpack2(u64 v) {
    float lo, hi;
    asm("mov.b64 {%0, %1}, %2;" : "=f"(lo), "=f"(hi) : "l"(v));
    return make_float2(lo, hi);
}

// ============================================================
// Tiled SGEMM: C[M,N] = A[M,K] @ op(B) (+bias) (+activation)
// NT: B is [N,K] row-major (dot of rows).  NN: B is [K,N] row-major.
// MODE 0: phi epilogue  -> g_phi, g_c=cos(phi), g_s=sin(phi)   (A = x)
// MODE 1: gate epilogue -> g_gate = sigmoid(.+bias)            (A = g_ca)
// MODE 2: plain         -> g_coupled                           (A = g_phi)
// BM=BN=64, BK=16, 256 threads, 4x4 thread tile.
// ============================================================
template <int MODE, bool NT>
__global__ __launch_bounds__(256) void sgemm_kernel(
    const float* __restrict__ A, const float* __restrict__ B,
    const float* __restrict__ bias, int M, int N, int K)
{
    __shared__ __align__(16) float As[16][64];
    __shared__ __align__(16) float Bs[16][64];

    const float* Ap = (MODE == 1) ? (const float*)g_ca
                    : (MODE == 2) ? (const float*)g_phi
                                  : A;

    const int bm = blockIdx.y * 64;
    const int bn = blockIdx.x * 64;
    const int tid = threadIdx.x;
    const int ty = tid >> 4;   // 0..15
    const int tx = tid & 15;   // 0..15

    float acc[4][4];
#pragma unroll
    for (int r = 0; r < 4; r++)
#pragma unroll
        for (int c = 0; c < 4; c++) acc[r][c] = 0.f;

    for (int k0 = 0; k0 < K; k0 += 16) {
        {   // A tile: 64 rows x 16 cols, transposed into As[k][m]
            int row = tid >> 2, cg = (tid & 3) << 2;
            float4 v = *(const float4*)(Ap + (size_t)(bm + row) * K + k0 + cg);
            As[cg + 0][row] = v.x; As[cg + 1][row] = v.y;
            As[cg + 2][row] = v.z; As[cg + 3][row] = v.w;
        }
        if (NT) {  // B[N,K]: same transpose pattern
            int row = tid >> 2, cg = (tid & 3) << 2;
            float4 v = *(const float4*)(B + (size_t)(bn + row) * K + k0 + cg);
            Bs[cg + 0][row] = v.x; Bs[cg + 1][row] = v.y;
            Bs[cg + 2][row] = v.z; Bs[cg + 3][row] = v.w;
        } else {   // B[K,N]: direct rows
            int kr = tid >> 4, nc = (tid & 15) << 2;
            *(float4*)&Bs[kr][nc] =
                *(const float4*)(B + (size_t)(k0 + kr) * N + bn + nc);
        }
        __syncthreads();

#pragma unroll
        for (int k = 0; k < 16; k++) {
            float4 av = *(const float4*)&As[k][ty << 2];
            float4 bv = *(const float4*)&Bs[k][tx << 2];
            float a0 = av.x, a1 = av.y, a2 = av.z, a3 = av.w;
            float b0 = bv.x, b1 = bv.y, b2 = bv.z, b3 = bv.w;
            acc[0][0] = fmaf(a0, b0, acc[0][0]); acc[0][1] = fmaf(a0, b1, acc[0][1]);
            acc[0][2] = fmaf(a0, b2, acc[0][2]); acc[0][3] = fmaf(a0, b3, acc[0][3]);
            acc[1][0] = fmaf(a1, b0, acc[1][0]); acc[1][1] = fmaf(a1, b1, acc[1][1]);
            acc[1][2] = fmaf(a1, b2, acc[1][2]); acc[1][3] = fmaf(a1, b3, acc[1][3]);
            acc[2][0] = fmaf(a2, b0, acc[2][0]); acc[2][1] = fmaf(a2, b1, acc[2][1]);
            acc[2][2] = fmaf(a2, b2, acc[2][2]); acc[2][3] = fmaf(a2, b3, acc[2][3]);
            acc[3][0] = fmaf(a3, b0, acc[3][0]); acc[3][1] = fmaf(a3, b1, acc[3][1]);
            acc[3][2] = fmaf(a3, b2, acc[3][2]); acc[3][3] = fmaf(a3, b3, acc[3][3]);
        }
        __syncthreads();
    }

#pragma unroll
    for (int r = 0; r < 4; r++) {
        int gm = bm + (ty << 2) + r;
        int gn0 = bn + (tx << 2);
        float4 v;
        float* vv = &v.x;
#pragma unroll
        for (int c = 0; c < 4; c++) {
            float t = acc[r][c];
            if (bias) t += bias[gn0 + c];
            vv[c] = t;
        }
        size_t idx = (size_t)gm * N + gn0;
        if (MODE == 0) {
            *(float4*)(g_phi + idx) = v;
            float4 cs, sn;
            sincosf(v.x, &sn.x, &cs.x);
            sincosf(v.y, &sn.y, &cs.y);
            sincosf(v.z, &sn.z, &cs.z);
            sincosf(v.w, &sn.w, &cs.w);
            *(float4*)(g_c + idx) = cs;
            *(float4*)(g_s + idx) = sn;
        } else if (MODE == 1) {
            float4 o;
            o.x = 1.f / (1.f + expf(-v.x));
            o.y = 1.f / (1.f + expf(-v.y));
            o.z = 1.f / (1.f + expf(-v.z));
            o.w = 1.f / (1.f + expf(-v.w));
            *(float4*)(g_gate + idx) = o;
        } else {
            *(float4*)(g_coupled + idx) = v;
        }
    }
}

// ============================================================
// Pairwise coherence: ca_update[b,i] = mean_j |c_i c_j + s_i s_j|
// grid = 512 blocks: (row b = blk>>1, half = blk&1), 256 threads,
// 2 consecutive i per thread, j packed in f32x2 pairs.
// ============================================================
__global__ __launch_bounds__(256) void pairwise_kernel(
    const float* __restrict__ prev_ca, float* __restrict__ out_ca)
{
    __shared__ __align__(16) float sc[DM];
    __shared__ __align__(16) float ss[DM];

    const int b = blockIdx.x >> 1;
    const int half = blockIdx.x & 1;
    const int tid = threadIdx.x;

    const float* crow = g_c + (size_t)b * DM;
    const float* srow = g_s + (size_t)b * DM;
    ((float4*)sc)[tid] = ((const float4*)crow)[tid];
    ((float4*)ss)[tid] = ((const float4*)srow)[tid];
    __syncthreads();

    const int i0 = half * 512 + tid * 2;
    const u64 ci0 = pack_dup(sc[i0]);
    const u64 si0 = pack_dup(ss[i0]);
    const u64 ci1 = pack_dup(sc[i0 + 1]);
    const u64 si1 = pack_dup(ss[i0 + 1]);

    u64 acc0 = 0ull, acc1 = 0ull;
    const u64 MASK = 0x7FFFFFFF7FFFFFFFULL;

    const u64* cj2 = (const u64*)sc;
    const u64* sj2 = (const u64*)ss;

#pragma unroll 8
    for (int j = 0; j < DM / 2; j++) {
        u64 cj = cj2[j];
        u64 sj = sj2[j];
        u64 t0 = f32x2_fma(ci0, cj, f32x2_mul(si0, sj));
        u64 t1 = f32x2_fma(ci1, cj, f32x2_mul(si1, sj));
        t0 &= MASK;   // |cos| on both lanes, ALU pipe
        t1 &= MASK;
        acc0 = f32x2_add(acc0, t0);
        acc1 = f32x2_add(acc1, t1);
    }

    float2 a0 = unpack2(acc0);
    float2 a1 = unpack2(acc1);
    float cau0 = (a0.x + a0.y) * (1.0f / (float)DM);
    float cau1 = (a1.x + a1.y) * (1.0f / (float)DM);

    size_t gi = (size_t)b * DM + i0;
    float ca0 = prev_ca[gi] * 0.95f + cau0 * 0.05f;
    float ca1 = prev_ca[gi + 1] * 0.95f + cau1 * 0.05f;
    g_ca[gi] = ca0;
    g_ca[gi + 1] = ca1;
    if (out_ca) {
        out_ca[gi] = ca0;
        out_ca[gi + 1] = ca1;
    }
}

// ============================================================
// features = LayerNorm(coupled * [gate,gate] + phi) * gamma + beta
// 1 block per batch row, 256 threads, 4 elements each.
// ============================================================
__global__ __launch_bounds__(256) void fuse_ln_kernel(
    const float* __restrict__ gamma, const float* __restrict__ beta,
    float* __restrict__ out_feat)
{
    const int b = blockIdx.x;
    const int tid = threadIdx.x;
    __shared__ float s1[8], s2[8];

    float h[4];
    float sum = 0.f, sumsq = 0.f;
#pragma unroll
    for (int q = 0; q < 4; q++) {
        int i = tid + q * 256;
        float g = g_gate[(size_t)b * DH + (i & (DH - 1))];
        float v = fmaf(g_coupled[(size_t)b * DM + i], g, g_phi[(size_t)b * DM + i]);
        h[q] = v;
        sum += v;
        sumsq = fmaf(v, v, sumsq);
    }
#pragma unroll
    for (int o = 16; o > 0; o >>= 1) {
        sum += __shfl_xor_sync(0xFFFFFFFFu, sum, o);
        sumsq += __shfl_xor_sync(0xFFFFFFFFu, sumsq, o);
    }
    int w = tid >> 5, l = tid & 31;
    if (l == 0) { s1[w] = sum; s2[w] = sumsq; }
    __syncthreads();
    if (w == 0) {
        float a = (l < 8) ? s1[l] : 0.f;
        float c = (l < 8) ? s2[l] : 0.f;
#pragma unroll
        for (int o = 4; o > 0; o >>= 1) {
            a += __shfl_xor_sync(0xFFFFFFFFu, a, o);
            c += __shfl_xor_sync(0xFFFFFFFFu, c, o);
        }
        if (l == 0) { s1[0] = a; s2[0] = c; }
    }
    __syncthreads();
    float mu = s1[0] * (1.0f / (float)DM);
    float var = s2[0] * (1.0f / (float)DM) - mu * mu;
    float inv = rsqrtf(var + 1e-5f);
#pragma unroll
    for (int q = 0; q < 4; q++) {
        int i = tid + q * 256;
        out_feat[(size_t)b * DM + i] = (h[q] - mu) * inv * gamma[i] + beta[i];
    }
}

// ============================================================
extern "C" void kernel_launch(void* const* d_in, const int* in_sizes, int n_in,
                              void* d_out, int out_size)
{
    const float* x       = (const float*)d_in[0];
    const float* prev_ca = (const float*)d_in[1];
    const float* Wp      = (const float*)d_in[2];
    const float* bp      = (const float*)d_in[3];
    const float* Wg      = (const float*)d_in[4];
    const float* bg      = (const float*)d_in[5];
    const float* W       = (const float*)d_in[6];
    const float* gamma   = (const float*)d_in[7];
    const float* beta    = (const float*)d_in[8];

    float* out = (float*)d_out;
    const int FEAT = BATCH * DM;               // 262144
    const int WSZ  = DM * DM;                  // 1048576
    float* out_ca = (out_size >= 2 * FEAT) ? out + FEAT : nullptr;
    float* out_W  = (out_size >= 2 * FEAT + WSZ) ? out + 2 * FEAT : nullptr;

    // phi = x @ Wp^T + bp  (+ sincos epilogue)
    sgemm_kernel<0, true><<<dim3(DM / 64, BATCH / 64), 256>>>(x, Wp, bp, BATCH, DM, NF);

    // ca = 0.95*prev_ca + 0.05*mean_j|cos(phi_i-phi_j)|
    pairwise_kernel<<<BATCH * 2, 256>>>(prev_ca, out_ca);

    // coupled = phi @ W   (NN)
    sgemm_kernel<2, false><<<dim3(DM / 64, BATCH / 64), 256>>>(nullptr, W, nullptr, BATCH, DM, DM);

    // gate = sigmoid(ca @ Wg^T + bg)  (NT)
    sgemm_kernel<1, true><<<dim3(DH / 64, BATCH / 64), 256>>>(nullptr, Wg, bg, BATCH, DH, DM);

    // features = LN(coupled * [gate,gate] + phi)
    fuse_ln_kernel<<<BATCH, 256>>>(gamma, beta, out);

    // third output: W passthrough
    if (out_W)
        cudaMemcpyAsync(out_W, W, (size_t)WSZ * sizeof(float),
                        cudaMemcpyDeviceToDevice, 0);
}

// round 2
// speedup vs baseline: 1.2844x; 1.2844x over previous
#include <cuda_runtime.h>
#include <math.h>

#define BATCH 256
#define NF 512
#define DM 1024
#define DH 512   // d_model/2

// -------- scratch (no allocations allowed) --------
__device__ float g_phi[BATCH * DM];
__device__ float g_c[BATCH * DM];
__device__ float g_s[BATCH * DM];
__device__ float g_ca[BATCH * DM];
__device__ float g_coupled[BATCH * DM];
__device__ float g_gate[BATCH * DH];

typedef unsigned long long u64;

// -------- packed fp32x2 helpers --------
__device__ __forceinline__ u64 f32x2_fma(u64 a, u64 b, u64 c) {
    u64 d;
    asm("fma.rn.f32x2 %0, %1, %2, %3;" : "=l"(d) : "l"(a), "l"(b), "l"(c));
    return d;
}
__device__ __forceinline__ u64 f32x2_mul(u64 a, u64 b) {
    u64 d;
    asm("mul.rn.f32x2 %0, %1, %2;" : "=l"(d) : "l"(a), "l"(b));
    return d;
}
__device__ __forceinline__ u64 f32x2_add(u64 a, u64 b) {
    u64 d;
    asm("add.rn.f32x2 %0, %1, %2;" : "=l"(d) : "l"(a), "l"(b));
    return d;
}
__device__ __forceinline__ u64 pack_dup(float v) {
    u64 r;
    asm("mov.b64 %0, {%1, %2};" : "=l"(r) : "f"(v), "f"(v));
    return r;
}
__device__ __forceinline__ float2 unpack2(u64 v) {
    float lo, hi;
    asm("mov.b64 {%0, %1}, %2;" : "=f"(lo), "=f"(hi) : "l"(v));
    return make_float2(lo, hi);
}

// ============================================================
// GEMM tiles: BM=32, BN=64, BK=16, 128 threads, 4x4 thread tile,
// inner loop in packed f32x2 (A operand lane-duplicated at staging).
// ============================================================

// ---- phi = x @ Wp^T + bp, plus sincos epilogue. grid (16, 8) ----
__global__ __launch_bounds__(128) void phi_gemm(
    const float* __restrict__ x, const float* __restrict__ Wp,
    const float* __restrict__ bp)
{
    __shared__ __align__(16) u64   As[16][32];   // lane-duplicated A
    __shared__ __align__(16) float Bs[16][64];

    const int bm = blockIdx.y * 32;
    const int bn = blockIdx.x * 64;
    const int tid = threadIdx.x;
    const int ty = tid >> 4;   // 0..7
    const int tx = tid & 15;   // 0..15

    u64 acc[4][2];
#pragma unroll
    for (int r = 0; r < 4; r++) { acc[r][0] = 0ull; acc[r][1] = 0ull; }

    const int row = tid >> 2, cg = (tid & 3) << 2;

    for (int k0 = 0; k0 < NF; k0 += 16) {
        {   // A tile: 32 rows x 16 k, duplicated into both f32 lanes
            float4 v = *(const float4*)(x + (size_t)(bm + row) * NF + k0 + cg);
            As[cg + 0][row] = pack_dup(v.x);
            As[cg + 1][row] = pack_dup(v.y);
            As[cg + 2][row] = pack_dup(v.z);
            As[cg + 3][row] = pack_dup(v.w);
        }
#pragma unroll
        for (int r2 = 0; r2 < 2; r2++) {  // B (NT): 64 rows x 16 k, transposed
            int brow = row + r2 * 32;
            float4 v = *(const float4*)(Wp + (size_t)(bn + brow) * NF + k0 + cg);
            Bs[cg + 0][brow] = v.x; Bs[cg + 1][brow] = v.y;
            Bs[cg + 2][brow] = v.z; Bs[cg + 3][brow] = v.w;
        }
        __syncthreads();

#pragma unroll
        for (int k = 0; k < 16; k++) {
            ulonglong2 a01 = *(const ulonglong2*)&As[k][ty << 2];
            ulonglong2 a23 = *(const ulonglong2*)&As[k][(ty << 2) + 2];
            double2 bd = *(const double2*)&Bs[k][tx << 2];
            u64 b0 = __double_as_longlong(bd.x);
            u64 b1 = __double_as_longlong(bd.y);
            acc[0][0] = f32x2_fma(a01.x, b0, acc[0][0]);
            acc[0][1] = f32x2_fma(a01.x, b1, acc[0][1]);
            acc[1][0] = f32x2_fma(a01.y, b0, acc[1][0]);
            acc[1][1] = f32x2_fma(a01.y, b1, acc[1][1]);
            acc[2][0] = f32x2_fma(a23.x, b0, acc[2][0]);
            acc[2][1] = f32x2_fma(a23.x, b1, acc[2][1]);
            acc[3][0] = f32x2_fma(a23.y, b0, acc[3][0]);
            acc[3][1] = f32x2_fma(a23.y, b1, acc[3][1]);
        }
        __syncthreads();
    }

    const int gn0 = bn + (tx << 2);
    float4 bias4 = *(const float4*)(bp + gn0);
#pragma unroll
    for (int r = 0; r < 4; r++) {
        float2 lo = unpack2(acc[r][0]);
        float2 hi = unpack2(acc[r][1]);
        float4 v;
        v.x = lo.x + bias4.x; v.y = lo.y + bias4.y;
        v.z = hi.x + bias4.z; v.w = hi.y + bias4.w;
        size_t idx = (size_t)(bm + (ty << 2) + r) * DM + gn0;
        *(float4*)(g_phi + idx) = v;
        float4 cs, sn;
        sincosf(v.x, &sn.x, &cs.x);
        sincosf(v.y, &sn.y, &cs.y);
        sincosf(v.z, &sn.z, &cs.z);
        sincosf(v.w, &sn.w, &cs.w);
        *(float4*)(g_c + idx) = cs;
        *(float4*)(g_s + idx) = sn;
    }
}

// ---- merged: coupled = phi@W (NN, bx<16) ++ gate = sigmoid(ca@Wg^T+bg)
//      (NT, bx>=16). Both K=1024. grid (24, 8) ----
__global__ __launch_bounds__(128) void coupled_gate_gemm(
    const float* __restrict__ W, const float* __restrict__ Wg,
    const float* __restrict__ bg)
{
    __shared__ __align__(16) u64   As[16][32];
    __shared__ __align__(16) float Bs[16][64];

    const bool is_gate = (blockIdx.x >= 16);
    const int bm = blockIdx.y * 32;
    const int bn = (is_gate ? (blockIdx.x - 16) : blockIdx.x) * 64;
    const int tid = threadIdx.x;
    const int ty = tid >> 4;
    const int tx = tid & 15;

    const float* Ap = is_gate ? (const float*)g_ca : (const float*)g_phi;

    u64 acc[4][2];
#pragma unroll
    for (int r = 0; r < 4; r++) { acc[r][0] = 0ull; acc[r][1] = 0ull; }

    const int row = tid >> 2, cg = (tid & 3) << 2;

    for (int k0 = 0; k0 < DM; k0 += 16) {
        {
            float4 v = *(const float4*)(Ap + (size_t)(bm + row) * DM + k0 + cg);
            As[cg + 0][row] = pack_dup(v.x);
            As[cg + 1][row] = pack_dup(v.y);
            As[cg + 2][row] = pack_dup(v.z);
            As[cg + 3][row] = pack_dup(v.w);
        }
        if (is_gate) {   // NT: Wg[N=512, K=1024]
#pragma unroll
            for (int r2 = 0; r2 < 2; r2++) {
                int brow = row + r2 * 32;
                float4 v = *(const float4*)(Wg + (size_t)(bn + brow) * DM + k0 + cg);
                Bs[cg + 0][brow] = v.x; Bs[cg + 1][brow] = v.y;
                Bs[cg + 2][brow] = v.z; Bs[cg + 3][brow] = v.w;
            }
        } else {          // NN: W[K=1024, N=1024]
            int kr = tid >> 3, nc = (tid & 7) << 3;
            *(float4*)&Bs[kr][nc] =
                *(const float4*)(W + (size_t)(k0 + kr) * DM + bn + nc);
            *(float4*)&Bs[kr][nc + 4] =
                *(const float4*)(W + (size_t)(k0 + kr) * DM + bn + nc + 4);
        }
        __syncthreads();

#pragma unroll
        for (int k = 0; k < 16; k++) {
            ulonglong2 a01 = *(const ulonglong2*)&As[k][ty << 2];
            ulonglong2 a23 = *(const ulonglong2*)&As[k][(ty << 2) + 2];
            double2 bd = *(const double2*)&Bs[k][tx << 2];
            u64 b0 = __double_as_longlong(bd.x);
            u64 b1 = __double_as_longlong(bd.y);
            acc[0][0] = f32x2_fma(a01.x, b0, acc[0][0]);
            acc[0][1] = f32x2_fma(a01.x, b1, acc[0][1]);
            acc[1][0] = f32x2_fma(a01.y, b0, acc[1][0]);
            acc[1][1] = f32x2_fma(a01.y, b1, acc[1][1]);
            acc[2][0] = f32x2_fma(a23.x, b0, acc[2][0]);
            acc[2][1] = f32x2_fma(a23.x, b1, acc[2][1]);
            acc[3][0] = f32x2_fma(a23.y, b0, acc[3][0]);
            acc[3][1] = f32x2_fma(a23.y, b1, acc[3][1]);
        }
        __syncthreads();
    }

    const int gn0 = bn + (tx << 2);
    if (is_gate) {
        float4 bias4 = *(const float4*)(bg + gn0);
#pragma unroll
        for (int r = 0; r < 4; r++) {
            float2 lo = unpack2(acc[r][0]);
            float2 hi = unpack2(acc[r][1]);
            float4 o;
            o.x = 1.f / (1.f + expf(-(lo.x + bias4.x)));
            o.y = 1.f / (1.f + expf(-(lo.y + bias4.y)));
            o.z = 1.f / (1.f + expf(-(hi.x + bias4.z)));
            o.w = 1.f / (1.f + expf(-(hi.y + bias4.w)));
            *(float4*)(g_gate + (size_t)(bm + (ty << 2) + r) * DH + gn0) = o;
        }
    } else {
#pragma unroll
        for (int r = 0; r < 4; r++) {
            float2 lo = unpack2(acc[r][0]);
            float2 hi = unpack2(acc[r][1]);
            float4 v = make_float4(lo.x, lo.y, hi.x, hi.y);
            *(float4*)(g_coupled + (size_t)(bm + (ty << 2) + r) * DM + gn0) = v;
        }
    }
}

// ============================================================
// Pairwise coherence: ca_update[b,i] = mean_j |c_i c_j + s_i s_j|
// ============================================================
__global__ __launch_bounds__(256) void pairwise_kernel(
    const float* __restrict__ prev_ca, float* __restrict__ out_ca)
{
    __shared__ __align__(16) float sc[DM];
    __shared__ __align__(16) float ss[DM];

    const int b = blockIdx.x >> 1;
    const int half = blockIdx.x & 1;
    const int tid = threadIdx.x;

    const float* crow = g_c + (size_t)b * DM;
    const float* srow = g_s + (size_t)b * DM;
    ((float4*)sc)[tid] = ((const float4*)crow)[tid];
    ((float4*)ss)[tid] = ((const float4*)srow)[tid];
    __syncthreads();

    const int i0 = half * 512 + tid * 2;
    const u64 ci0 = pack_dup(sc[i0]);
    const u64 si0 = pack_dup(ss[i0]);
    const u64 ci1 = pack_dup(sc[i0 + 1]);
    const u64 si1 = pack_dup(ss[i0 + 1]);

    u64 acc0 = 0ull, acc1 = 0ull;
    const u64 MASK = 0x7FFFFFFF7FFFFFFFULL;

    const u64* cj2 = (const u64*)sc;
    const u64* sj2 = (const u64*)ss;

#pragma unroll 8
    for (int j = 0; j < DM / 2; j++) {
        u64 cj = cj2[j];
        u64 sj = sj2[j];
        u64 t0 = f32x2_fma(ci0, cj, f32x2_mul(si0, sj));
        u64 t1 = f32x2_fma(ci1, cj, f32x2_mul(si1, sj));
        t0 &= MASK;
        t1 &= MASK;
        acc0 = f32x2_add(acc0, t0);
        acc1 = f32x2_add(acc1, t1);
    }

    float2 a0 = unpack2(acc0);
    float2 a1 = unpack2(acc1);
    float cau0 = (a0.x + a0.y) * (1.0f / (float)DM);
    float cau1 = (a1.x + a1.y) * (1.0f / (float)DM);

    size_t gi = (size_t)b * DM + i0;
    float ca0 = prev_ca[gi] * 0.95f + cau0 * 0.05f;
    float ca1 = prev_ca[gi + 1] * 0.95f + cau1 * 0.05f;
    g_ca[gi] = ca0;
    g_ca[gi + 1] = ca1;
    if (out_ca) {
        out_ca[gi] = ca0;
        out_ca[gi + 1] = ca1;
    }
}

// ============================================================
// features = LayerNorm(coupled * [gate,gate] + phi) * gamma + beta
// ============================================================
__global__ __launch_bounds__(256) void fuse_ln_kernel(
    const float* __restrict__ gamma, const float* __restrict__ beta,
    float* __restrict__ out_feat)
{
    const int b = blockIdx.x;
    const int tid = threadIdx.x;
    __shared__ float s1[8], s2[8];

    float h[4];
    float sum = 0.f, sumsq = 0.f;
#pragma unroll
    for (int q = 0; q < 4; q++) {
        int i = tid + q * 256;
        float g = g_gate[(size_t)b * DH + (i & (DH - 1))];
        float v = fmaf(g_coupled[(size_t)b * DM + i], g, g_phi[(size_t)b * DM + i]);
        h[q] = v;
        sum += v;
        sumsq = fmaf(v, v, sumsq);
    }
#pragma unroll
    for (int o = 16; o > 0; o >>= 1) {
        sum += __shfl_xor_sync(0xFFFFFFFFu, sum, o);
        sumsq += __shfl_xor_sync(0xFFFFFFFFu, sumsq, o);
    }
    int w = tid >> 5, l = tid & 31;
    if (l == 0) { s1[w] = sum; s2[w] = sumsq; }
    __syncthreads();
    if (w == 0) {
        float a = (l < 8) ? s1[l] : 0.f;
        float c = (l < 8) ? s2[l] : 0.f;
#pragma unroll
        for (int o = 4; o > 0; o >>= 1) {
            a += __shfl_xor_sync(0xFFFFFFFFu, a, o);
            c += __shfl_xor_sync(0xFFFFFFFFu, c, o);
        }
        if (l == 0) { s1[0] = a; s2[0] = c; }
    }
    __syncthreads();
    float mu = s1[0] * (1.0f / (float)DM);
    float var = s2[0] * (1.0f / (float)DM) - mu * mu;
    float inv = rsqrtf(var + 1e-5f);
#pragma unroll
    for (int q = 0; q < 4; q++) {
        int i = tid + q * 256;
        out_feat[(size_t)b * DM + i] = (h[q] - mu) * inv * gamma[i] + beta[i];
    }
}

// ============================================================
extern "C" void kernel_launch(void* const* d_in, const int* in_sizes, int n_in,
                              void* d_out, int out_size)
{
    const float* x       = (const float*)d_in[0];
    const float* prev_ca = (const float*)d_in[1];
    const float* Wp      = (const float*)d_in[2];
    const float* bp      = (const float*)d_in[3];
    const float* Wg      = (const float*)d_in[4];
    const float* bg      = (const float*)d_in[5];
    const float* W       = (const float*)d_in[6];
    const float* gamma   = (const float*)d_in[7];
    const float* beta    = (const float*)d_in[8];

    float* out = (float*)d_out;
    const int FEAT = BATCH * DM;               // 262144
    const int WSZ  = DM * DM;                  // 1048576
    float* out_ca = (out_size >= 2 * FEAT) ? out + FEAT : nullptr;
    float* out_W  = (out_size >= 2 * FEAT + WSZ) ? out + 2 * FEAT : nullptr;

    // phi = x @ Wp^T + bp  (+ sincos epilogue): 128 blocks
    phi_gemm<<<dim3(DM / 64, BATCH / 32), 128>>>(x, Wp, bp);

    // ca = 0.95*prev_ca + 0.05*mean_j|cos(phi_i-phi_j)|: 512 blocks
    pairwise_kernel<<<BATCH * 2, 256>>>(prev_ca, out_ca);

    // coupled = phi@W (NN) merged with gate = sigmoid(ca@Wg^T+bg) (NT): 192 blocks
    coupled_gate_gemm<<<dim3(DM / 64 + DH / 64, BATCH / 32), 128>>>(W, Wg, bg);

    // features = LN(coupled * [gate,gate] + phi): 256 blocks
    fuse_ln_kernel<<<BATCH, 256>>>(gamma, beta, out);

    // third output: W passthrough
    if (out_W)
        cudaMemcpyAsync(out_W, W, (size_t)WSZ * sizeof(float),
                        cudaMemcpyDeviceToDevice, 0);
}

// round 3
// speedup vs baseline: 2.1607x; 1.6823x over previous
#include <cuda_runtime.h>
#include <math.h>

#define BATCH 256
#define NF 512
#define DM 1024
#define DH 512
#define KH 32          // Fourier harmonics for |cos|

// -------- scratch --------
__device__ float g_php[2][BATCH * DM];   // phi split-K partials
__device__ float g_phi[BATCH * DM];
__device__ float g_ca[BATCH * DM];
__device__ float g_cp[2][BATCH * DM];    // coupled split-K partials
__device__ float g_gt[2][BATCH * DH];    // gate pre-act split-K partials

typedef unsigned long long u64;

__device__ __forceinline__ u64 f32x2_fma(u64 a, u64 b, u64 c) {
    u64 d;
    asm("fma.rn.f32x2 %0, %1, %2, %3;" : "=l"(d) : "l"(a), "l"(b), "l"(c));
    return d;
}
__device__ __forceinline__ u64 pack_dup(float v) {
    u64 r;
    asm("mov.b64 %0, {%1, %2};" : "=l"(r) : "f"(v), "f"(v));
    return r;
}
__device__ __forceinline__ float2 unpack2(u64 v) {
    float lo, hi;
    asm("mov.b64 {%0, %1}, %2;" : "=f"(lo), "=f"(hi) : "l"(v));
    return make_float2(lo, hi);
}

// ============================================================
// phi partial GEMM: g_php[z] = x @ Wp^T (K-half z). grid (16,8,2)
// BM=32, BN=64, BK=16, 128 threads, packed f32x2 inner loop.
// ============================================================
__global__ __launch_bounds__(128) void phi_gemm(
    const float* __restrict__ x, const float* __restrict__ Wp)
{
    __shared__ __align__(16) u64   As[16][32];
    __shared__ __align__(16) float Bs[16][64];

    const int bm = blockIdx.y * 32;
    const int bn = blockIdx.x * 64;
    const int z  = blockIdx.z;
    const int tid = threadIdx.x;
    const int ty = tid >> 4, tx = tid & 15;

    u64 acc[4][2];
#pragma unroll
    for (int r = 0; r < 4; r++) { acc[r][0] = 0ull; acc[r][1] = 0ull; }

    const int row = tid >> 2, cg = (tid & 3) << 2;
    const int kbeg = z * (NF / 2), kend = kbeg + NF / 2;

    for (int k0 = kbeg; k0 < kend; k0 += 16) {
        {
            float4 v = *(const float4*)(x + (size_t)(bm + row) * NF + k0 + cg);
            As[cg + 0][row] = pack_dup(v.x);
            As[cg + 1][row] = pack_dup(v.y);
            As[cg + 2][row] = pack_dup(v.z);
            As[cg + 3][row] = pack_dup(v.w);
        }
#pragma unroll
        for (int r2 = 0; r2 < 2; r2++) {
            int brow = row + r2 * 32;
            float4 v = *(const float4*)(Wp + (size_t)(bn + brow) * NF + k0 + cg);
            Bs[cg + 0][brow] = v.x; Bs[cg + 1][brow] = v.y;
            Bs[cg + 2][brow] = v.z; Bs[cg + 3][brow] = v.w;
        }
        __syncthreads();

#pragma unroll
        for (int k = 0; k < 16; k++) {
            ulonglong2 a01 = *(const ulonglong2*)&As[k][ty << 2];
            ulonglong2 a23 = *(const ulonglong2*)&As[k][(ty << 2) + 2];
            double2 bd = *(const double2*)&Bs[k][tx << 2];
            u64 b0 = __double_as_longlong(bd.x);
            u64 b1 = __double_as_longlong(bd.y);
            acc[0][0] = f32x2_fma(a01.x, b0, acc[0][0]);
            acc[0][1] = f32x2_fma(a01.x, b1, acc[0][1]);
            acc[1][0] = f32x2_fma(a01.y, b0, acc[1][0]);
            acc[1][1] = f32x2_fma(a01.y, b1, acc[1][1]);
            acc[2][0] = f32x2_fma(a23.x, b0, acc[2][0]);
            acc[2][1] = f32x2_fma(a23.x, b1, acc[2][1]);
            acc[3][0] = f32x2_fma(a23.y, b0, acc[3][0]);
            acc[3][1] = f32x2_fma(a23.y, b1, acc[3][1]);
        }
        __syncthreads();
    }

    const int gn0 = bn + (tx << 2);
#pragma unroll
    for (int r = 0; r < 4; r++) {
        float2 lo = unpack2(acc[r][0]);
        float2 hi = unpack2(acc[r][1]);
        *(float4*)(&g_php[z][(size_t)(bm + (ty << 2) + r) * DM + gn0]) =
            make_float4(lo.x, lo.y, hi.x, hi.y);
    }
}

// ============================================================
// ca_kernel: one block per batch row.
//   phi = php0+php1+bp; store g_phi
//   harmonics C_k = sum_j cos(2k phi_j), S_k likewise (Chebyshev recurrence)
//   ca_update_i = 2/pi + sum_k coef_k (cos2kphi_i*C_k + sin2kphi_i*S_k)/D
//   ca = 0.95 prev + 0.05 upd  -> g_ca, out_ca
// ============================================================
__global__ __launch_bounds__(256) void ca_kernel(
    const float* __restrict__ prev_ca, const float* __restrict__ bp,
    float* __restrict__ out_ca)
{
    __shared__ float wP[KH][8];
    __shared__ float wQ[KH][8];
    __shared__ float shC[KH];
    __shared__ float shS[KH];

    const int b = blockIdx.x;
    const int tid = threadIdx.x;
    const int warp = tid >> 5, lane = tid & 31;
    const int j0 = tid * 4;

    // combine phi partials + bias
    float4 p0 = *(const float4*)(&g_php[0][(size_t)b * DM + j0]);
    float4 p1 = *(const float4*)(&g_php[1][(size_t)b * DM + j0]);
    float4 bb = *(const float4*)(bp + j0);
    float phi[4] = { p0.x + p1.x + bb.x, p0.y + p1.y + bb.y,
                     p0.z + p1.z + bb.z, p0.w + p1.w + bb.w };
    *(float4*)(&g_phi[(size_t)b * DM + j0]) =
        make_float4(phi[0], phi[1], phi[2], phi[3]);

    // recurrence seeds: theta = 2*phi
    float c1[4], s1[4], t[4], ck[4], sk[4], cm[4], sm[4];
#pragma unroll
    for (int q = 0; q < 4; q++) {
        sincosf(2.0f * phi[q], &s1[q], &c1[q]);
        t[q] = 2.0f * c1[q];
        ck[q] = c1[q]; sk[q] = s1[q];
        cm[q] = 1.0f;  sm[q] = 0.0f;
    }

    // ---- phase 1: harmonic sums ----
#pragma unroll 4
    for (int k = 0; k < KH; k++) {
        float p = ck[0] + ck[1] + ck[2] + ck[3];
        float q_ = sk[0] + sk[1] + sk[2] + sk[3];
#pragma unroll
        for (int o = 16; o > 0; o >>= 1) {
            p  += __shfl_xor_sync(0xFFFFFFFFu, p, o);
            q_ += __shfl_xor_sync(0xFFFFFFFFu, q_, o);
        }
        if (lane == 0) { wP[k][warp] = p; wQ[k][warp] = q_; }
        // advance recurrence
#pragma unroll
        for (int q = 0; q < 4; q++) {
            float cn = fmaf(t[q], ck[q], -cm[q]);
            float sn = fmaf(t[q], sk[q], -sm[q]);
            cm[q] = ck[q]; ck[q] = cn;
            sm[q] = sk[q]; sk[q] = sn;
        }
    }
    __syncthreads();

    if (tid < KH) {
        float C = 0.f, S = 0.f;
#pragma unroll
        for (int w = 0; w < 8; w++) { C += wP[tid][w]; S += wQ[tid][w]; }
        int m = tid + 1;
        float coef = ((m & 1) ? 1.0f : -1.0f) *
                     (4.0f / 3.14159265358979f) / (float)(4 * m * m - 1);
        coef *= (1.0f / (float)DM);
        shC[tid] = C * coef;
        shS[tid] = S * coef;
    }
    __syncthreads();

    // ---- phase 2: per-i reconstruction (restart recurrence) ----
    float acc[4] = { 0.63661977f, 0.63661977f, 0.63661977f, 0.63661977f }; // 2/pi
#pragma unroll
    for (int q = 0; q < 4; q++) {
        ck[q] = c1[q]; sk[q] = s1[q];
        cm[q] = 1.0f;  sm[q] = 0.0f;
    }
#pragma unroll 4
    for (int k = 0; k < KH; k++) {
        float C = shC[k], S = shS[k];
#pragma unroll
        for (int q = 0; q < 4; q++) {
            acc[q] = fmaf(ck[q], C, acc[q]);
            acc[q] = fmaf(sk[q], S, acc[q]);
            float cn = fmaf(t[q], ck[q], -cm[q]);
            float sn = fmaf(t[q], sk[q], -sm[q]);
            cm[q] = ck[q]; ck[q] = cn;
            sm[q] = sk[q]; sk[q] = sn;
        }
    }

    float4 pc = *(const float4*)(prev_ca + (size_t)b * DM + j0);
    float4 ca;
    ca.x = pc.x * 0.95f + acc[0] * 0.05f;
    ca.y = pc.y * 0.95f + acc[1] * 0.05f;
    ca.z = pc.z * 0.95f + acc[2] * 0.05f;
    ca.w = pc.w * 0.95f + acc[3] * 0.05f;
    *(float4*)(&g_ca[(size_t)b * DM + j0]) = ca;
    if (out_ca) *(float4*)(out_ca + (size_t)b * DM + j0) = ca;
}

// ============================================================
// merged split-K GEMM: coupled = phi@W (NN, bx<16), gate-preact =
// ca@Wg^T (NT, bx>=16). z = K-half. grid (24, 8, 2), 128 threads.
// ============================================================
__global__ __launch_bounds__(128) void coupled_gate_gemm(
    const float* __restrict__ W, const float* __restrict__ Wg)
{
    __shared__ __align__(16) u64   As[16][32];
    __shared__ __align__(16) float Bs[16][64];

    const bool is_gate = (blockIdx.x >= 16);
    const int bm = blockIdx.y * 32;
    const int bn = (is_gate ? (blockIdx.x - 16) : blockIdx.x) * 64;
    const int z  = blockIdx.z;
    const int tid = threadIdx.x;
    const int ty = tid >> 4, tx = tid & 15;

    const float* Ap = is_gate ? (const float*)g_ca : (const float*)g_phi;

    u64 acc[4][2];
#pragma unroll
    for (int r = 0; r < 4; r++) { acc[r][0] = 0ull; acc[r][1] = 0ull; }

    const int row = tid >> 2, cg = (tid & 3) << 2;
    const int kbeg = z * (DM / 2), kend = kbeg + DM / 2;

    for (int k0 = kbeg; k0 < kend; k0 += 16) {
        {
            float4 v = *(const float4*)(Ap + (size_t)(bm + row) * DM + k0 + cg);
            As[cg + 0][row] = pack_dup(v.x);
            As[cg + 1][row] = pack_dup(v.y);
            As[cg + 2][row] = pack_dup(v.z);
            As[cg + 3][row] = pack_dup(v.w);
        }
        if (is_gate) {
#pragma unroll
            for (int r2 = 0; r2 < 2; r2++) {
                int brow = row + r2 * 32;
                float4 v = *(const float4*)(Wg + (size_t)(bn + brow) * DM + k0 + cg);
                Bs[cg + 0][brow] = v.x; Bs[cg + 1][brow] = v.y;
                Bs[cg + 2][brow] = v.z; Bs[cg + 3][brow] = v.w;
            }
        } else {
            int kr = tid >> 3, nc = (tid & 7) << 3;
            *(float4*)&Bs[kr][nc] =
                *(const float4*)(W + (size_t)(k0 + kr) * DM + bn + nc);
            *(float4*)&Bs[kr][nc + 4] =
                *(const float4*)(W + (size_t)(k0 + kr) * DM + bn + nc + 4);
        }
        __syncthreads();

#pragma unroll
        for (int k = 0; k < 16; k++) {
            ulonglong2 a01 = *(const ulonglong2*)&As[k][ty << 2];
            ulonglong2 a23 = *(const ulonglong2*)&As[k][(ty << 2) + 2];
            double2 bd = *(const double2*)&Bs[k][tx << 2];
            u64 b0 = __double_as_longlong(bd.x);
            u64 b1 = __double_as_longlong(bd.y);
            acc[0][0] = f32x2_fma(a01.x, b0, acc[0][0]);
            acc[0][1] = f32x2_fma(a01.x, b1, acc[0][1]);
            acc[1][0] = f32x2_fma(a01.y, b0, acc[1][0]);
            acc[1][1] = f32x2_fma(a01.y, b1, acc[1][1]);
            acc[2][0] = f32x2_fma(a23.x, b0, acc[2][0]);
            acc[2][1] = f32x2_fma(a23.x, b1, acc[2][1]);
            acc[3][0] = f32x2_fma(a23.y, b0, acc[3][0]);
            acc[3][1] = f32x2_fma(a23.y, b1, acc[3][1]);
        }
        __syncthreads();
    }

    const int gn0 = bn + (tx << 2);
    float* dst = is_gate ? g_gt[z] : g_cp[z];
    const int ld = is_gate ? DH : DM;
#pragma unroll
    for (int r = 0; r < 4; r++) {
        float2 lo = unpack2(acc[r][0]);
        float2 hi = unpack2(acc[r][1]);
        *(float4*)(&dst[(size_t)(bm + (ty << 2) + r) * ld + gn0]) =
            make_float4(lo.x, lo.y, hi.x, hi.y);
    }
}

// ============================================================
// features = LN( (cp0+cp1) * sigmoid(gt0+gt1+bg)[tiled] + phi )
// ============================================================
__global__ __launch_bounds__(256) void fuse_ln_kernel(
    const float* __restrict__ bg,
    const float* __restrict__ gamma, const float* __restrict__ beta,
    float* __restrict__ out_feat)
{
    const int b = blockIdx.x;
    const int tid = threadIdx.x;
    __shared__ float s1[8], s2[8];

    float h[4];
    float sum = 0.f, sumsq = 0.f;
#pragma unroll
    for (int q = 0; q < 4; q++) {
        int i = tid + q * 256;
        int gi = i & (DH - 1);
        float gpre = g_gt[0][(size_t)b * DH + gi] + g_gt[1][(size_t)b * DH + gi] + bg[gi];
        float g = 1.f / (1.f + expf(-gpre));
        float cp = g_cp[0][(size_t)b * DM + i] + g_cp[1][(size_t)b * DM + i];
        float v = fmaf(cp, g, g_phi[(size_t)b * DM + i]);
        h[q] = v;
        sum += v;
        sumsq = fmaf(v, v, sumsq);
    }
#pragma unroll
    for (int o = 16; o > 0; o >>= 1) {
        sum += __shfl_xor_sync(0xFFFFFFFFu, sum, o);
        sumsq += __shfl_xor_sync(0xFFFFFFFFu, sumsq, o);
    }
    int w = tid >> 5, l = tid & 31;
    if (l == 0) { s1[w] = sum; s2[w] = sumsq; }
    __syncthreads();
    if (w == 0) {
        float a = (l < 8) ? s1[l] : 0.f;
        float c = (l < 8) ? s2[l] : 0.f;
#pragma unroll
        for (int o = 4; o > 0; o >>= 1) {
            a += __shfl_xor_sync(0xFFFFFFFFu, a, o);
            c += __shfl_xor_sync(0xFFFFFFFFu, c, o);
        }
        if (l == 0) { s1[0] = a; s2[0] = c; }
    }
    __syncthreads();
    float mu = s1[0] * (1.0f / (float)DM);
    float var = s2[0] * (1.0f / (float)DM) - mu * mu;
    float inv = rsqrtf(var + 1e-5f);
#pragma unroll
    for (int q = 0; q < 4; q++) {
        int i = tid + q * 256;
        out_feat[(size_t)b * DM + i] = (h[q] - mu) * inv * gamma[i] + beta[i];
    }
}

// ============================================================
extern "C" void kernel_launch(void* const* d_in, const int* in_sizes, int n_in,
                              void* d_out, int out_size)
{
    const float* x       = (const float*)d_in[0];
    const float* prev_ca = (const float*)d_in[1];
    const float* Wp      = (const float*)d_in[2];
    const float* bp      = (const float*)d_in[3];
    const float* Wg      = (const float*)d_in[4];
    const float* bg      = (const float*)d_in[5];
    const float* W       = (const float*)d_in[6];
    const float* gamma   = (const float*)d_in[7];
    const float* beta    = (const float*)d_in[8];

    float* out = (float*)d_out;
    const int FEAT = BATCH * DM;
    const int WSZ  = DM * DM;
    float* out_ca = (out_size >= 2 * FEAT) ? out + FEAT : nullptr;
    float* out_W  = (out_size >= 2 * FEAT + WSZ) ? out + 2 * FEAT : nullptr;

    // phi partials (split-K): 256 blocks
    phi_gemm<<<dim3(DM / 64, BATCH / 32, 2), 128>>>(x, Wp);

    // phi combine + Fourier-harmonic coherence + ca: 256 blocks
    ca_kernel<<<BATCH, 256>>>(prev_ca, bp, out_ca);

    // coupled + gate pre-act (split-K): 384 blocks
    coupled_gate_gemm<<<dim3(DM / 64 + DH / 64, BATCH / 32, 2), 128>>>(W, Wg);

    // LN epilogue
    fuse_ln_kernel<<<BATCH, 256>>>(bg, gamma, beta, out);

    // W passthrough
    if (out_W)
        cudaMemcpyAsync(out_W, W, (size_t)WSZ * sizeof(float),
                        cudaMemcpyDeviceToDevice, 0);
}

// round 4
// speedup vs baseline: 2.4010x; 1.1112x over previous
#include <cuda_runtime.h>
#include <math.h>

#define BATCH 256
#define NF 512
#define DM 1024
#define DH 512
#define KH 16          // Fourier harmonics for |cos|
#define ZC 4           // split-K factor for coupled/gate

// -------- scratch --------
__device__ float g_php[2][BATCH * DM];    // phi split-K partials
__device__ float g_phi[BATCH * DM];
__device__ float g_ca[BATCH * DM];
__device__ float g_cp[ZC][BATCH * DM];    // coupled split-K partials
__device__ float g_gt[ZC][BATCH * DH];    // gate pre-act split-K partials

typedef unsigned long long u64;

__device__ __forceinline__ u64 f32x2_fma(u64 a, u64 b, u64 c) {
    u64 d;
    asm("fma.rn.f32x2 %0, %1, %2, %3;" : "=l"(d) : "l"(a), "l"(b), "l"(c));
    return d;
}
__device__ __forceinline__ u64 pack_dup(float v) {
    u64 r;
    asm("mov.b64 %0, {%1, %2};" : "=l"(r) : "f"(v), "f"(v));
    return r;
}
__device__ __forceinline__ float2 unpack2(u64 v) {
    float lo, hi;
    asm("mov.b64 {%0, %1}, %2;" : "=f"(lo), "=f"(hi) : "l"(v));
    return make_float2(lo, hi);
}

// ============================================================
// phi partial GEMM: g_php[z] = x @ Wp^T (K-half z). grid (16,8,2)
// ============================================================
__global__ __launch_bounds__(128) void phi_gemm(
    const float* __restrict__ x, const float* __restrict__ Wp)
{
    __shared__ __align__(16) u64   As[16][32];
    __shared__ __align__(16) float Bs[16][64];

    const int bm = blockIdx.y * 32;
    const int bn = blockIdx.x * 64;
    const int z  = blockIdx.z;
    const int tid = threadIdx.x;
    const int ty = tid >> 4, tx = tid & 15;

    u64 acc[4][2];
#pragma unroll
    for (int r = 0; r < 4; r++) { acc[r][0] = 0ull; acc[r][1] = 0ull; }

    const int row = tid >> 2, cg = (tid & 3) << 2;
    const int kbeg = z * (NF / 2), kend = kbeg + NF / 2;

    for (int k0 = kbeg; k0 < kend; k0 += 16) {
        {
            float4 v = *(const float4*)(x + (size_t)(bm + row) * NF + k0 + cg);
            As[cg + 0][row] = pack_dup(v.x);
            As[cg + 1][row] = pack_dup(v.y);
            As[cg + 2][row] = pack_dup(v.z);
            As[cg + 3][row] = pack_dup(v.w);
        }
#pragma unroll
        for (int r2 = 0; r2 < 2; r2++) {
            int brow = row + r2 * 32;
            float4 v = *(const float4*)(Wp + (size_t)(bn + brow) * NF + k0 + cg);
            Bs[cg + 0][brow] = v.x; Bs[cg + 1][brow] = v.y;
            Bs[cg + 2][brow] = v.z; Bs[cg + 3][brow] = v.w;
        }
        __syncthreads();

#pragma unroll
        for (int k = 0; k < 16; k++) {
            ulonglong2 a01 = *(const ulonglong2*)&As[k][ty << 2];
            ulonglong2 a23 = *(const ulonglong2*)&As[k][(ty << 2) + 2];
            double2 bd = *(const double2*)&Bs[k][tx << 2];
            u64 b0 = __double_as_longlong(bd.x);
            u64 b1 = __double_as_longlong(bd.y);
            acc[0][0] = f32x2_fma(a01.x, b0, acc[0][0]);
            acc[0][1] = f32x2_fma(a01.x, b1, acc[0][1]);
            acc[1][0] = f32x2_fma(a01.y, b0, acc[1][0]);
            acc[1][1] = f32x2_fma(a01.y, b1, acc[1][1]);
            acc[2][0] = f32x2_fma(a23.x, b0, acc[2][0]);
            acc[2][1] = f32x2_fma(a23.x, b1, acc[2][1]);
            acc[3][0] = f32x2_fma(a23.y, b0, acc[3][0]);
            acc[3][1] = f32x2_fma(a23.y, b1, acc[3][1]);
        }
        __syncthreads();
    }

    const int gn0 = bn + (tx << 2);
#pragma unroll
    for (int r = 0; r < 4; r++) {
        float2 lo = unpack2(acc[r][0]);
        float2 hi = unpack2(acc[r][1]);
        *(float4*)(&g_php[z][(size_t)(bm + (ty << 2) + r) * DM + gn0]) =
            make_float4(lo.x, lo.y, hi.x, hi.y);
    }
}

// ============================================================
// ca_kernel: one block per batch row. Fourier-harmonic coherence.
// Reduction via padded smem transpose (not long shuffle chains).
// ============================================================
__global__ __launch_bounds__(256) void ca_kernel(
    const float* __restrict__ prev_ca, const float* __restrict__ bp,
    float* __restrict__ out_ca)
{
    __shared__ float red[2 * KH][257];   // [harmonic(C:0-15,S:16-31)][thread]
    __shared__ float shC[KH];
    __shared__ float shS[KH];

    const int b = blockIdx.x;
    const int tid = threadIdx.x;
    const int warp = tid >> 5, lane = tid & 31;
    const int j0 = tid * 4;

    // combine phi partials + bias
    float4 p0 = *(const float4*)(&g_php[0][(size_t)b * DM + j0]);
    float4 p1 = *(const float4*)(&g_php[1][(size_t)b * DM + j0]);
    float4 bb = *(const float4*)(bp + j0);
    float phi[4] = { p0.x + p1.x + bb.x, p0.y + p1.y + bb.y,
                     p0.z + p1.z + bb.z, p0.w + p1.w + bb.w };
    *(float4*)(&g_phi[(size_t)b * DM + j0]) =
        make_float4(phi[0], phi[1], phi[2], phi[3]);

    // Chebyshev recurrence seeds: theta = 2*phi
    float c1[4], s1[4], t[4], ck[4], sk[4], cm[4], sm[4];
#pragma unroll
    for (int q = 0; q < 4; q++) {
        sincosf(2.0f * phi[q], &s1[q], &c1[q]);
        t[q] = 2.0f * c1[q];
        ck[q] = c1[q]; sk[q] = s1[q];
        cm[q] = 1.0f;  sm[q] = 0.0f;
    }

    // ---- phase 1: per-thread partial harmonic sums into smem ----
#pragma unroll
    for (int k = 0; k < KH; k++) {
        red[k][tid]      = ck[0] + ck[1] + ck[2] + ck[3];
        red[k + KH][tid] = sk[0] + sk[1] + sk[2] + sk[3];
#pragma unroll
        for (int q = 0; q < 4; q++) {
            float cn = fmaf(t[q], ck[q], -cm[q]);
            float sn = fmaf(t[q], sk[q], -sm[q]);
            cm[q] = ck[q]; ck[q] = cn;
            sm[q] = sk[q]; sk[q] = sn;
        }
    }
    __syncthreads();

    // ---- reduce: warp w handles harmonics 4w..4w+3 ----
#pragma unroll
    for (int h = 0; h < 4; h++) {
        int hh = warp * 4 + h;        // 0..31
        float v = red[hh][lane] + red[hh][lane + 32] +
                  red[hh][lane + 64] + red[hh][lane + 96] +
                  red[hh][lane + 128] + red[hh][lane + 160] +
                  red[hh][lane + 192] + red[hh][lane + 224];
#pragma unroll
        for (int o = 16; o > 0; o >>= 1)
            v += __shfl_xor_sync(0xFFFFFFFFu, v, o);
        if (lane == 0) {
            int m = (hh & (KH - 1)) + 1;
            float coef = ((m & 1) ? 1.0f : -1.0f) *
                         (4.0f / 3.14159265358979f) / (float)(4 * m * m - 1) *
                         (1.0f / (float)DM);
            if (hh < KH) shC[hh] = v * coef;
            else         shS[hh - KH] = v * coef;
        }
    }
    __syncthreads();

    // ---- phase 2: per-i reconstruction ----
    float acc[4] = { 0.63661977f, 0.63661977f, 0.63661977f, 0.63661977f };
#pragma unroll
    for (int q = 0; q < 4; q++) {
        ck[q] = c1[q]; sk[q] = s1[q];
        cm[q] = 1.0f;  sm[q] = 0.0f;
    }
#pragma unroll
    for (int k = 0; k < KH; k++) {
        float C = shC[k], S = shS[k];
#pragma unroll
        for (int q = 0; q < 4; q++) {
            acc[q] = fmaf(ck[q], C, acc[q]);
            acc[q] = fmaf(sk[q], S, acc[q]);
            float cn = fmaf(t[q], ck[q], -cm[q]);
            float sn = fmaf(t[q], sk[q], -sm[q]);
            cm[q] = ck[q]; ck[q] = cn;
            sm[q] = sk[q]; sk[q] = sn;
        }
    }

    float4 pc = *(const float4*)(prev_ca + (size_t)b * DM + j0);
    float4 ca;
    ca.x = pc.x * 0.95f + acc[0] * 0.05f;
    ca.y = pc.y * 0.95f + acc[1] * 0.05f;
    ca.z = pc.z * 0.95f + acc[2] * 0.05f;
    ca.w = pc.w * 0.95f + acc[3] * 0.05f;
    *(float4*)(&g_ca[(size_t)b * DM + j0]) = ca;
    if (out_ca) *(float4*)(out_ca + (size_t)b * DM + j0) = ca;
}

// ============================================================
// merged split-K GEMM: coupled = phi@W (NN, bx<16), gate-preact =
// ca@Wg^T (NT, bx>=16). z = K-quarter. grid (24, 8, ZC), 128 thr.
// ============================================================
__global__ __launch_bounds__(128) void coupled_gate_gemm(
    const float* __restrict__ W, const float* __restrict__ Wg)
{
    __shared__ __align__(16) u64   As[16][32];
    __shared__ __align__(16) float Bs[16][64];

    const bool is_gate = (blockIdx.x >= 16);
    const int bm = blockIdx.y * 32;
    const int bn = (is_gate ? (blockIdx.x - 16) : blockIdx.x) * 64;
    const int z  = blockIdx.z;
    const int tid = threadIdx.x;
    const int ty = tid >> 4, tx = tid & 15;

    const float* Ap = is_gate ? (const float*)g_ca : (const float*)g_phi;

    u64 acc[4][2];
#pragma unroll
    for (int r = 0; r < 4; r++) { acc[r][0] = 0ull; acc[r][1] = 0ull; }

    const int row = tid >> 2, cg = (tid & 3) << 2;
    const int kbeg = z * (DM / ZC), kend = kbeg + DM / ZC;

    for (int k0 = kbeg; k0 < kend; k0 += 16) {
        {
            float4 v = *(const float4*)(Ap + (size_t)(bm + row) * DM + k0 + cg);
            As[cg + 0][row] = pack_dup(v.x);
            As[cg + 1][row] = pack_dup(v.y);
            As[cg + 2][row] = pack_dup(v.z);
            As[cg + 3][row] = pack_dup(v.w);
        }
        if (is_gate) {
#pragma unroll
            for (int r2 = 0; r2 < 2; r2++) {
                int brow = row + r2 * 32;
                float4 v = *(const float4*)(Wg + (size_t)(bn + brow) * DM + k0 + cg);
                Bs[cg + 0][brow] = v.x; Bs[cg + 1][brow] = v.y;
                Bs[cg + 2][brow] = v.z; Bs[cg + 3][brow] = v.w;
            }
        } else {
            int kr = tid >> 3, nc = (tid & 7) << 3;
            *(float4*)&Bs[kr][nc] =
                *(const float4*)(W + (size_t)(k0 + kr) * DM + bn + nc);
            *(float4*)&Bs[kr][nc + 4] =
                *(const float4*)(W + (size_t)(k0 + kr) * DM + bn + nc + 4);
        }
        __syncthreads();

#pragma unroll
        for (int k = 0; k < 16; k++) {
            ulonglong2 a01 = *(const ulonglong2*)&As[k][ty << 2];
            ulonglong2 a23 = *(const ulonglong2*)&As[k][(ty << 2) + 2];
            double2 bd = *(const double2*)&Bs[k][tx << 2];
            u64 b0 = __double_as_longlong(bd.x);
            u64 b1 = __double_as_longlong(bd.y);
            acc[0][0] = f32x2_fma(a01.x, b0, acc[0][0]);
            acc[0][1] = f32x2_fma(a01.x, b1, acc[0][1]);
            acc[1][0] = f32x2_fma(a01.y, b0, acc[1][0]);
            acc[1][1] = f32x2_fma(a01.y, b1, acc[1][1]);
            acc[2][0] = f32x2_fma(a23.x, b0, acc[2][0]);
            acc[2][1] = f32x2_fma(a23.x, b1, acc[2][1]);
            acc[3][0] = f32x2_fma(a23.y, b0, acc[3][0]);
            acc[3][1] = f32x2_fma(a23.y, b1, acc[3][1]);
        }
        __syncthreads();
    }

    const int gn0 = bn + (tx << 2);
    float* dst = is_gate ? g_gt[z] : g_cp[z];
    const int ld = is_gate ? DH : DM;
#pragma unroll
    for (int r = 0; r < 4; r++) {
        float2 lo = unpack2(acc[r][0]);
        float2 hi = unpack2(acc[r][1]);
        *(float4*)(&dst[(size_t)(bm + (ty << 2) + r) * ld + gn0]) =
            make_float4(lo.x, lo.y, hi.x, hi.y);
    }
}

// ============================================================
// blocks <256: features = LN( Σcp * sigmoid(Σgt+bg)[tiled] + phi )
// blocks >=256: W passthrough copy (4MB spread over 256 blocks)
// ============================================================
__global__ __launch_bounds__(256) void fuse_ln_kernel(
    const float* __restrict__ bg,
    const float* __restrict__ gamma, const float* __restrict__ beta,
    const float* __restrict__ W,
    float* __restrict__ out_feat, float* __restrict__ out_W)
{
    const int tid = threadIdx.x;

    if (blockIdx.x >= BATCH) {   // W copy: 4096 floats per block
        if (out_W) {
            size_t base = (size_t)(blockIdx.x - BATCH) * 4096 + tid * 4;
#pragma unroll
            for (int q = 0; q < 4; q++) {
                *(float4*)(out_W + base + q * 1024) =
                    *(const float4*)(W + base + q * 1024);
            }
        }
        return;
    }

    const int b = blockIdx.x;
    __shared__ float s1[8], s2[8];

    float h[4];
    float sum = 0.f, sumsq = 0.f;
#pragma unroll
    for (int q = 0; q < 4; q++) {
        int i = tid + q * 256;
        int gi = i & (DH - 1);
        float gpre = bg[gi];
#pragma unroll
        for (int zz = 0; zz < ZC; zz++) gpre += g_gt[zz][(size_t)b * DH + gi];
        float g = 1.f / (1.f + expf(-gpre));
        float cp = 0.f;
#pragma unroll
        for (int zz = 0; zz < ZC; zz++) cp += g_cp[zz][(size_t)b * DM + i];
        float v = fmaf(cp, g, g_phi[(size_t)b * DM + i]);
        h[q] = v;
        sum += v;
        sumsq = fmaf(v, v, sumsq);
    }
#pragma unroll
    for (int o = 16; o > 0; o >>= 1) {
        sum += __shfl_xor_sync(0xFFFFFFFFu, sum, o);
        sumsq += __shfl_xor_sync(0xFFFFFFFFu, sumsq, o);
    }
    int w = tid >> 5, l = tid & 31;
    if (l == 0) { s1[w] = sum; s2[w] = sumsq; }
    __syncthreads();
    if (w == 0) {
        float a = (l < 8) ? s1[l] : 0.f;
        float c = (l < 8) ? s2[l] : 0.f;
#pragma unroll
        for (int o = 4; o > 0; o >>= 1) {
            a += __shfl_xor_sync(0xFFFFFFFFu, a, o);
            c += __shfl_xor_sync(0xFFFFFFFFu, c, o);
        }
        if (l == 0) { s1[0] = a; s2[0] = c; }
    }
    __syncthreads();
    float mu = s1[0] * (1.0f / (float)DM);
    float var = s2[0] * (1.0f / (float)DM) - mu * mu;
    float inv = rsqrtf(var + 1e-5f);
#pragma unroll
    for (int q = 0; q < 4; q++) {
        int i = tid + q * 256;
        out_feat[(size_t)b * DM + i] = (h[q] - mu) * inv * gamma[i] + beta[i];
    }
}

// ============================================================
extern "C" void kernel_launch(void* const* d_in, const int* in_sizes, int n_in,
                              void* d_out, int out_size)
{
    const float* x       = (const float*)d_in[0];
    const float* prev_ca = (const float*)d_in[1];
    const float* Wp      = (const float*)d_in[2];
    const float* bp      = (const float*)d_in[3];
    const float* Wg      = (const float*)d_in[4];
    const float* bg      = (const float*)d_in[5];
    const float* W       = (const float*)d_in[6];
    const float* gamma   = (const float*)d_in[7];
    const float* beta    = (const float*)d_in[8];

    float* out = (float*)d_out;
    const int FEAT = BATCH * DM;
    const int WSZ  = DM * DM;
    float* out_ca = (out_size >= 2 * FEAT) ? out + FEAT : nullptr;
    float* out_W  = (out_size >= 2 * FEAT + WSZ) ? out + 2 * FEAT : nullptr;

    // phi partials (split-K x2): 256 blocks
    phi_gemm<<<dim3(DM / 64, BATCH / 32, 2), 128>>>(x, Wp);

    // phi combine + Fourier coherence + ca: 256 blocks
    ca_kernel<<<BATCH, 256>>>(prev_ca, bp, out_ca);

    // coupled + gate pre-act (split-K x4): 768 blocks
    coupled_gate_gemm<<<dim3(DM / 64 + DH / 64, BATCH / 32, ZC), 128>>>(W, Wg);

    // LN epilogue + W passthrough copy: 512 blocks
    fuse_ln_kernel<<<BATCH + 256, 256>>>(bg, gamma, beta, W, out, out_W);
}

// round 5
// speedup vs baseline: 3.0432x; 1.2675x over previous
#include <cuda_runtime.h>
#include <math.h>

#define BATCH 256
#define NF 512
#define DM 1024
#define DH 512
#define KH 16          // Fourier harmonics for |cos|
#define ZP 4           // split-K factor for phi
#define ZC 4           // split-K factor for coupled/gate

// -------- scratch --------
__device__ float g_php[ZP][BATCH * DM];   // phi split-K partials
__device__ float g_phi[BATCH * DM];
__device__ float g_ca[BATCH * DM];
__device__ float g_cp[ZC][BATCH * DM];    // coupled split-K partials
__device__ float g_gt[ZC][BATCH * DH];    // gate pre-act split-K partials

typedef unsigned long long u64;

__device__ __forceinline__ u64 f32x2_fma(u64 a, u64 b, u64 c) {
    u64 d;
    asm("fma.rn.f32x2 %0, %1, %2, %3;" : "=l"(d) : "l"(a), "l"(b), "l"(c));
    return d;
}
__device__ __forceinline__ u64 pack_dup(float v) {
    u64 r;
    asm("mov.b64 %0, {%1, %2};" : "=l"(r) : "f"(v), "f"(v));
    return r;
}
__device__ __forceinline__ float2 unpack2(u64 v) {
    float lo, hi;
    asm("mov.b64 {%0, %1}, %2;" : "=f"(lo), "=f"(hi) : "l"(v));
    return make_float2(lo, hi);
}

// ============================================================
// GEMM tiling: BM=64, BN=64, BK=16, 128 threads, 8x4 thread tile.
// Inner loop: 4 broadcast LDS.128 (A, lane-dup u64) + 1 LDS.128 (B)
// per k-step feeding 16 FFMA2 (32 FMA-issue cycles).
// ============================================================

// ---- phi partials: g_php[z] = x @ Wp^T (K-quarter z). grid (16,4,ZP) ----
__global__ __launch_bounds__(128) void phi_gemm(
    const float* __restrict__ x, const float* __restrict__ Wp)
{
    __shared__ __align__(16) u64   As[16][64];   // 8KB, lane-duplicated A
    __shared__ __align__(16) float Bs[16][64];   // 4KB

    const int bm = blockIdx.y * 64;
    const int bn = blockIdx.x * 64;
    const int z  = blockIdx.z;
    const int tid = threadIdx.x;
    const int ty = tid >> 4, tx = tid & 15;
    const int ry = ty * 8, cx = tx * 4;

    u64 acc[8][2];
#pragma unroll
    for (int r = 0; r < 8; r++) { acc[r][0] = 0ull; acc[r][1] = 0ull; }

    const int arow = tid >> 1, akh = (tid & 1) * 8;
    const int kbeg = z * (NF / ZP), kend = kbeg + NF / ZP;

    for (int k0 = kbeg; k0 < kend; k0 += 16) {
        {   // A: x[bm+arow][k0+akh .. +7] -> dup u64
            const float* src = x + (size_t)(bm + arow) * NF + k0 + akh;
            float4 v0 = *(const float4*)(src);
            float4 v1 = *(const float4*)(src + 4);
            As[akh + 0][arow] = pack_dup(v0.x); As[akh + 1][arow] = pack_dup(v0.y);
            As[akh + 2][arow] = pack_dup(v0.z); As[akh + 3][arow] = pack_dup(v0.w);
            As[akh + 4][arow] = pack_dup(v1.x); As[akh + 5][arow] = pack_dup(v1.y);
            As[akh + 6][arow] = pack_dup(v1.z); As[akh + 7][arow] = pack_dup(v1.w);
        }
        {   // B (NT): Wp[bn+arow][k0+akh .. +7] -> transposed
            const float* src = Wp + (size_t)(bn + arow) * NF + k0 + akh;
            float4 v0 = *(const float4*)(src);
            float4 v1 = *(const float4*)(src + 4);
            Bs[akh + 0][arow] = v0.x; Bs[akh + 1][arow] = v0.y;
            Bs[akh + 2][arow] = v0.z; Bs[akh + 3][arow] = v0.w;
            Bs[akh + 4][arow] = v1.x; Bs[akh + 5][arow] = v1.y;
            Bs[akh + 6][arow] = v1.z; Bs[akh + 7][arow] = v1.w;
        }
        __syncthreads();

#pragma unroll
        for (int k = 0; k < 16; k++) {
            ulonglong2 a01 = *(const ulonglong2*)&As[k][ry];
            ulonglong2 a23 = *(const ulonglong2*)&As[k][ry + 2];
            ulonglong2 a45 = *(const ulonglong2*)&As[k][ry + 4];
            ulonglong2 a67 = *(const ulonglong2*)&As[k][ry + 6];
            double2 bd = *(const double2*)&Bs[k][cx];
            u64 b0 = __double_as_longlong(bd.x);
            u64 b1 = __double_as_longlong(bd.y);
            acc[0][0] = f32x2_fma(a01.x, b0, acc[0][0]);
            acc[0][1] = f32x2_fma(a01.x, b1, acc[0][1]);
            acc[1][0] = f32x2_fma(a01.y, b0, acc[1][0]);
            acc[1][1] = f32x2_fma(a01.y, b1, acc[1][1]);
            acc[2][0] = f32x2_fma(a23.x, b0, acc[2][0]);
            acc[2][1] = f32x2_fma(a23.x, b1, acc[2][1]);
            acc[3][0] = f32x2_fma(a23.y, b0, acc[3][0]);
            acc[3][1] = f32x2_fma(a23.y, b1, acc[3][1]);
            acc[4][0] = f32x2_fma(a45.x, b0, acc[4][0]);
            acc[4][1] = f32x2_fma(a45.x, b1, acc[4][1]);
            acc[5][0] = f32x2_fma(a45.y, b0, acc[5][0]);
            acc[5][1] = f32x2_fma(a45.y, b1, acc[5][1]);
            acc[6][0] = f32x2_fma(a67.x, b0, acc[6][0]);
            acc[6][1] = f32x2_fma(a67.x, b1, acc[6][1]);
            acc[7][0] = f32x2_fma(a67.y, b0, acc[7][0]);
            acc[7][1] = f32x2_fma(a67.y, b1, acc[7][1]);
        }
        __syncthreads();
    }

    const int gn0 = bn + cx;
#pragma unroll
    for (int r = 0; r < 8; r++) {
        float2 lo = unpack2(acc[r][0]);
        float2 hi = unpack2(acc[r][1]);
        *(float4*)(&g_php[z][(size_t)(bm + ry + r) * DM + gn0]) =
            make_float4(lo.x, lo.y, hi.x, hi.y);
    }
}

// ============================================================
// ca_kernel: one block per batch row. Fourier-harmonic coherence.
// ============================================================
__global__ __launch_bounds__(256) void ca_kernel(
    const float* __restrict__ prev_ca, const float* __restrict__ bp,
    float* __restrict__ out_ca)
{
    __shared__ float red[2 * KH][257];
    __shared__ float shC[KH];
    __shared__ float shS[KH];

    const int b = blockIdx.x;
    const int tid = threadIdx.x;
    const int warp = tid >> 5, lane = tid & 31;
    const int j0 = tid * 4;

    // combine phi partials + bias
    float4 bb = *(const float4*)(bp + j0);
    float phi[4] = { bb.x, bb.y, bb.z, bb.w };
#pragma unroll
    for (int zz = 0; zz < ZP; zz++) {
        float4 p = *(const float4*)(&g_php[zz][(size_t)b * DM + j0]);
        phi[0] += p.x; phi[1] += p.y; phi[2] += p.z; phi[3] += p.w;
    }
    *(float4*)(&g_phi[(size_t)b * DM + j0]) =
        make_float4(phi[0], phi[1], phi[2], phi[3]);

    // Chebyshev recurrence seeds: theta = 2*phi
    float c1[4], s1[4], t[4], ck[4], sk[4], cm[4], sm[4];
#pragma unroll
    for (int q = 0; q < 4; q++) {
        sincosf(2.0f * phi[q], &s1[q], &c1[q]);
        t[q] = 2.0f * c1[q];
        ck[q] = c1[q]; sk[q] = s1[q];
        cm[q] = 1.0f;  sm[q] = 0.0f;
    }

    // ---- phase 1: per-thread partial harmonic sums into smem ----
#pragma unroll
    for (int k = 0; k < KH; k++) {
        red[k][tid]      = ck[0] + ck[1] + ck[2] + ck[3];
        red[k + KH][tid] = sk[0] + sk[1] + sk[2] + sk[3];
#pragma unroll
        for (int q = 0; q < 4; q++) {
            float cn = fmaf(t[q], ck[q], -cm[q]);
            float sn = fmaf(t[q], sk[q], -sm[q]);
            cm[q] = ck[q]; ck[q] = cn;
            sm[q] = sk[q]; sk[q] = sn;
        }
    }
    __syncthreads();

    // ---- reduce: warp w handles harmonics 4w..4w+3 ----
#pragma unroll
    for (int h = 0; h < 4; h++) {
        int hh = warp * 4 + h;
        float v = red[hh][lane] + red[hh][lane + 32] +
                  red[hh][lane + 64] + red[hh][lane + 96] +
                  red[hh][lane + 128] + red[hh][lane + 160] +
                  red[hh][lane + 192] + red[hh][lane + 224];
#pragma unroll
        for (int o = 16; o > 0; o >>= 1)
            v += __shfl_xor_sync(0xFFFFFFFFu, v, o);
        if (lane == 0) {
            int m = (hh & (KH - 1)) + 1;
            float coef = ((m & 1) ? 1.0f : -1.0f) *
                         (4.0f / 3.14159265358979f) / (float)(4 * m * m - 1) *
                         (1.0f / (float)DM);
            if (hh < KH) shC[hh] = v * coef;
            else         shS[hh - KH] = v * coef;
        }
    }
    __syncthreads();

    // ---- phase 2: per-i reconstruction ----
    float acc[4] = { 0.63661977f, 0.63661977f, 0.63661977f, 0.63661977f };
#pragma unroll
    for (int q = 0; q < 4; q++) {
        ck[q] = c1[q]; sk[q] = s1[q];
        cm[q] = 1.0f;  sm[q] = 0.0f;
    }
#pragma unroll
    for (int k = 0; k < KH; k++) {
        float C = shC[k], S = shS[k];
#pragma unroll
        for (int q = 0; q < 4; q++) {
            acc[q] = fmaf(ck[q], C, acc[q]);
            acc[q] = fmaf(sk[q], S, acc[q]);
            float cn = fmaf(t[q], ck[q], -cm[q]);
            float sn = fmaf(t[q], sk[q], -sm[q]);
            cm[q] = ck[q]; ck[q] = cn;
            sm[q] = sk[q]; sk[q] = sn;
        }
    }

    float4 pc = *(const float4*)(prev_ca + (size_t)b * DM + j0);
    float4 ca;
    ca.x = pc.x * 0.95f + acc[0] * 0.05f;
    ca.y = pc.y * 0.95f + acc[1] * 0.05f;
    ca.z = pc.z * 0.95f + acc[2] * 0.05f;
    ca.w = pc.w * 0.95f + acc[3] * 0.05f;
    *(float4*)(&g_ca[(size_t)b * DM + j0]) = ca;
    if (out_ca) *(float4*)(out_ca + (size_t)b * DM + j0) = ca;
}

// ============================================================
// merged split-K GEMM: coupled = phi@W (NN, bx<16), gate-preact =
// ca@Wg^T (NT, bx>=16). grid (24, 4, ZC), 128 threads, 8x4 tile.
// ============================================================
__global__ __launch_bounds__(128) void coupled_gate_gemm(
    const float* __restrict__ W, const float* __restrict__ Wg)
{
    __shared__ __align__(16) u64   As[16][64];
    __shared__ __align__(16) float Bs[16][64];

    const bool is_gate = (blockIdx.x >= 16);
    const int bm = blockIdx.y * 64;
    const int bn = (is_gate ? (blockIdx.x - 16) : blockIdx.x) * 64;
    const int z  = blockIdx.z;
    const int tid = threadIdx.x;
    const int ty = tid >> 4, tx = tid & 15;
    const int ry = ty * 8, cx = tx * 4;

    const float* Ap = is_gate ? (const float*)g_ca : (const float*)g_phi;

    u64 acc[8][2];
#pragma unroll
    for (int r = 0; r < 8; r++) { acc[r][0] = 0ull; acc[r][1] = 0ull; }

    const int arow = tid >> 1, akh = (tid & 1) * 8;
    const int kbeg = z * (DM / ZC), kend = kbeg + DM / ZC;

    for (int k0 = kbeg; k0 < kend; k0 += 16) {
        {   // A: Ap[bm+arow][k0+akh .. +7] -> dup u64
            const float* src = Ap + (size_t)(bm + arow) * DM + k0 + akh;
            float4 v0 = *(const float4*)(src);
            float4 v1 = *(const float4*)(src + 4);
            As[akh + 0][arow] = pack_dup(v0.x); As[akh + 1][arow] = pack_dup(v0.y);
            As[akh + 2][arow] = pack_dup(v0.z); As[akh + 3][arow] = pack_dup(v0.w);
            As[akh + 4][arow] = pack_dup(v1.x); As[akh + 5][arow] = pack_dup(v1.y);
            As[akh + 6][arow] = pack_dup(v1.z); As[akh + 7][arow] = pack_dup(v1.w);
        }
        if (is_gate) {   // NT: Wg[bn+arow][k0+akh .. +7]
            const float* src = Wg + (size_t)(bn + arow) * DM + k0 + akh;
            float4 v0 = *(const float4*)(src);
            float4 v1 = *(const float4*)(src + 4);
            Bs[akh + 0][arow] = v0.x; Bs[akh + 1][arow] = v0.y;
            Bs[akh + 2][arow] = v0.z; Bs[akh + 3][arow] = v0.w;
            Bs[akh + 4][arow] = v1.x; Bs[akh + 5][arow] = v1.y;
            Bs[akh + 6][arow] = v1.z; Bs[akh + 7][arow] = v1.w;
        } else {          // NN: W[k0+kr][bn+nc..]
            int kr = tid >> 3, nc = (tid & 7) << 3;
            const float* src = W + (size_t)(k0 + kr) * DM + bn + nc;
            *(float4*)&Bs[kr][nc]     = *(const float4*)(src);
            *(float4*)&Bs[kr][nc + 4] = *(const float4*)(src + 4);
        }
        __syncthreads();

#pragma unroll
        for (int k = 0; k < 16; k++) {
            ulonglong2 a01 = *(const ulonglong2*)&As[k][ry];
            ulonglong2 a23 = *(const ulonglong2*)&As[k][ry + 2];
            ulonglong2 a45 = *(const ulonglong2*)&As[k][ry + 4];
            ulonglong2 a67 = *(const ulonglong2*)&As[k][ry + 6];
            double2 bd = *(const double2*)&Bs[k][cx];
            u64 b0 = __double_as_longlong(bd.x);
            u64 b1 = __double_as_longlong(bd.y);
            acc[0][0] = f32x2_fma(a01.x, b0, acc[0][0]);
            acc[0][1] = f32x2_fma(a01.x, b1, acc[0][1]);
            acc[1][0] = f32x2_fma(a01.y, b0, acc[1][0]);
            acc[1][1] = f32x2_fma(a01.y, b1, acc[1][1]);
            acc[2][0] = f32x2_fma(a23.x, b0, acc[2][0]);
            acc[2][1] = f32x2_fma(a23.x, b1, acc[2][1]);
            acc[3][0] = f32x2_fma(a23.y, b0, acc[3][0]);
            acc[3][1] = f32x2_fma(a23.y, b1, acc[3][1]);
            acc[4][0] = f32x2_fma(a45.x, b0, acc[4][0]);
            acc[4][1] = f32x2_fma(a45.x, b1, acc[4][1]);
            acc[5][0] = f32x2_fma(a45.y, b0, acc[5][0]);
            acc[5][1] = f32x2_fma(a45.y, b1, acc[5][1]);
            acc[6][0] = f32x2_fma(a67.x, b0, acc[6][0]);
            acc[6][1] = f32x2_fma(a67.x, b1, acc[6][1]);
            acc[7][0] = f32x2_fma(a67.y, b0, acc[7][0]);
            acc[7][1] = f32x2_fma(a67.y, b1, acc[7][1]);
        }
        __syncthreads();
    }

    const int gn0 = bn + cx;
    float* dst = is_gate ? g_gt[z] : g_cp[z];
    const int ld = is_gate ? DH : DM;
#pragma unroll
    for (int r = 0; r < 8; r++) {
        float2 lo = unpack2(acc[r][0]);
        float2 hi = unpack2(acc[r][1]);
        *(float4*)(&dst[(size_t)(bm + ry + r) * ld + gn0]) =
            make_float4(lo.x, lo.y, hi.x, hi.y);
    }
}

// ============================================================
// blocks <256: features = LN( Σcp * sigmoid(Σgt+bg)[tiled] + phi )
// blocks >=256: W passthrough copy
// ============================================================
__global__ __launch_bounds__(256) void fuse_ln_kernel(
    const float* __restrict__ bg,
    const float* __restrict__ gamma, const float* __restrict__ beta,
    const float* __restrict__ W,
    float* __restrict__ out_feat, float* __restrict__ out_W)
{
    const int tid = threadIdx.x;

    if (blockIdx.x >= BATCH) {
        if (out_W) {
            size_t base = (size_t)(blockIdx.x - BATCH) * 4096 + tid * 4;
#pragma unroll
            for (int q = 0; q < 4; q++) {
                *(float4*)(out_W + base + q * 1024) =
                    *(const float4*)(W + base + q * 1024);
            }
        }
        return;
    }

    const int b = blockIdx.x;
    __shared__ float s1[8], s2[8];

    float h[4];
    float sum = 0.f, sumsq = 0.f;
#pragma unroll
    for (int q = 0; q < 4; q++) {
        int i = tid + q * 256;
        int gi = i & (DH - 1);
        float gpre = bg[gi];
#pragma unroll
        for (int zz = 0; zz < ZC; zz++) gpre += g_gt[zz][(size_t)b * DH + gi];
        float g = 1.f / (1.f + expf(-gpre));
        float cp = 0.f;
#pragma unroll
        for (int zz = 0; zz < ZC; zz++) cp += g_cp[zz][(size_t)b * DM + i];
        float v = fmaf(cp, g, g_phi[(size_t)b * DM + i]);
        h[q] = v;
        sum += v;
        sumsq = fmaf(v, v, sumsq);
    }
#pragma unroll
    for (int o = 16; o > 0; o >>= 1) {
        sum += __shfl_xor_sync(0xFFFFFFFFu, sum, o);
        sumsq += __shfl_xor_sync(0xFFFFFFFFu, sumsq, o);
    }
    int w = tid >> 5, l = tid & 31;
    if (l == 0) { s1[w] = sum; s2[w] = sumsq; }
    __syncthreads();
    if (w == 0) {
        float a = (l < 8) ? s1[l] : 0.f;
        float c = (l < 8) ? s2[l] : 0.f;
#pragma unroll
        for (int o = 4; o > 0; o >>= 1) {
            a += __shfl_xor_sync(0xFFFFFFFFu, a, o);
            c += __shfl_xor_sync(0xFFFFFFFFu, c, o);
        }
        if (l == 0) { s1[0] = a; s2[0] = c; }
    }
    __syncthreads();
    float mu = s1[0] * (1.0f / (float)DM);
    float var = s2[0] * (1.0f / (float)DM) - mu * mu;
    float inv = rsqrtf(var + 1e-5f);
#pragma unroll
    for (int q = 0; q < 4; q++) {
        int i = tid + q * 256;
        out_feat[(size_t)b * DM + i] = (h[q] - mu) * inv * gamma[i] + beta[i];
    }
}

// ============================================================
extern "C" void kernel_launch(void* const* d_in, const int* in_sizes, int n_in,
                              void* d_out, int out_size)
{
    const float* x       = (const float*)d_in[0];
    const float* prev_ca = (const float*)d_in[1];
    const float* Wp      = (const float*)d_in[2];
    const float* bp      = (const float*)d_in[3];
    const float* Wg      = (const float*)d_in[4];
    const float* bg      = (const float*)d_in[5];
    const float* W       = (const float*)d_in[6];
    const float* gamma   = (const float*)d_in[7];
    const float* beta    = (const float*)d_in[8];

    float* out = (float*)d_out;
    const int FEAT = BATCH * DM;
    const int WSZ  = DM * DM;
    float* out_ca = (out_size >= 2 * FEAT) ? out + FEAT : nullptr;
    float* out_W  = (out_size >= 2 * FEAT + WSZ) ? out + 2 * FEAT : nullptr;

    // phi partials (split-K x4): 256 blocks
    phi_gemm<<<dim3(DM / 64, BATCH / 64, ZP), 128>>>(x, Wp);

    // phi combine + Fourier coherence + ca: 256 blocks
    ca_kernel<<<BATCH, 256>>>(prev_ca, bp, out_ca);

    // coupled + gate pre-act (split-K x4): 384 blocks
    coupled_gate_gemm<<<dim3(DM / 64 + DH / 64, BATCH / 64, ZC), 128>>>(W, Wg);

    // LN epilogue + W passthrough copy: 512 blocks
    fuse_ln_kernel<<<BATCH + 256, 256>>>(bg, gamma, beta, W, out, out_W);
}